// round 1
// baseline (speedup 1.0000x reference)
#include <cuda_runtime.h>
#include <math_constants.h>

// Problem constants: x (64, 4096, 256) fp32, top-8 over axis 1 (S), sorted desc.
#define B_DIM 64
#define S_DIM 4096
#define C_DIM 256
#define K_TOP 8
#define CHUNKS 8
#define CHUNK_S (S_DIM / CHUNKS)   // 512

// Scratch for partial top-8s: [B][CHUNKS][K_TOP][C] = 4 MiB (static, no alloc).
__device__ float g_partial[B_DIM * CHUNKS * K_TOP * C_DIM];

__device__ __forceinline__ void topk_insert(float (&t)[K_TOP], float v) {
    if (v > t[K_TOP - 1]) {
        t[K_TOP - 1] = v;
        #pragma unroll
        for (int i = K_TOP - 1; i > 0; --i) {
            if (t[i] > t[i - 1]) {
                float tmp = t[i - 1]; t[i - 1] = t[i]; t[i] = tmp;
            } else {
                break;
            }
        }
    }
}

// Pass 1: one thread per channel, one block per (batch, chunk).
// Warp loads are fully coalesced (32 consecutive channels = 128B).
__global__ __launch_bounds__(C_DIM) void kmax_partial_kernel(
    const float* __restrict__ x)
{
    const int batch = blockIdx.x / CHUNKS;
    const int chunk = blockIdx.x % CHUNKS;
    const int c = threadIdx.x;

    const float* __restrict__ p =
        x + (size_t)batch * S_DIM * C_DIM + (size_t)chunk * CHUNK_S * C_DIM + c;

    float t[K_TOP];
    #pragma unroll
    for (int i = 0; i < K_TOP; ++i) t[i] = -CUDART_INF_F;

    // 8-way unroll: batch the loads first for MLP=8, then the compares.
    #pragma unroll 1
    for (int s = 0; s < CHUNK_S; s += 8) {
        float v[8];
        #pragma unroll
        for (int u = 0; u < 8; ++u)
            v[u] = p[(size_t)(s + u) * C_DIM];
        #pragma unroll
        for (int u = 0; u < 8; ++u)
            topk_insert(t, v[u]);
    }

    float* __restrict__ out =
        g_partial + ((size_t)(batch * CHUNKS + chunk) * K_TOP) * C_DIM + c;
    #pragma unroll
    for (int k = 0; k < K_TOP; ++k)
        out[(size_t)k * C_DIM] = t[k];
}

// Pass 2: merge CHUNKS partial top-8s per (b, c) into final sorted top-8.
// Output layout: out[b][k][c].
__global__ __launch_bounds__(256) void kmax_merge_kernel(float* __restrict__ out)
{
    const int tid = blockIdx.x * blockDim.x + threadIdx.x;
    if (tid >= B_DIM * C_DIM) return;
    const int b = tid / C_DIM;
    const int c = tid % C_DIM;

    float t[K_TOP];
    #pragma unroll
    for (int i = 0; i < K_TOP; ++i) t[i] = -CUDART_INF_F;

    const float* __restrict__ p =
        g_partial + ((size_t)b * CHUNKS * K_TOP) * C_DIM + c;
    #pragma unroll
    for (int j = 0; j < CHUNKS * K_TOP; ++j)
        topk_insert(t, p[(size_t)j * C_DIM]);

    float* __restrict__ o = out + (size_t)b * K_TOP * C_DIM + c;
    #pragma unroll
    for (int k = 0; k < K_TOP; ++k)
        o[(size_t)k * C_DIM] = t[k];
}

extern "C" void kernel_launch(void* const* d_in, const int* in_sizes, int n_in,
                              void* d_out, int out_size) {
    const float* x = (const float*)d_in[0];
    float* out = (float*)d_out;

    kmax_partial_kernel<<<B_DIM * CHUNKS, C_DIM>>>(x);
    kmax_merge_kernel<<<(B_DIM * C_DIM + 255) / 256, 256>>>(out);
}

// round 2
// speedup vs baseline: 1.5204x; 1.5204x over previous
#include <cuda_runtime.h>
#include <math_constants.h>

// x: (64, 4096, 256) fp32; top-8 over axis 1 (S), sorted descending -> (64, 8, 256)
#define B_DIM 64
#define S_DIM 4096
#define C_DIM 256
#define K_TOP 8

#define CHUNKS 16
#define CHUNK_S (S_DIM / CHUNKS)       // 256
#define LANES 64                       // float4 lanes covering 256 channels
#define PAIRS_PER_BLOCK 4              // 256 threads = 4 (b,chunk) pairs
#define N_PAIRS (B_DIM * CHUNKS)       // 1024
#define GRID1 (N_PAIRS / PAIRS_PER_BLOCK)  // 256 blocks

// Partial top-8s: [B][CHUNKS][K_TOP][C] = 8 MiB static scratch (no allocation).
__device__ float g_partial[B_DIM * CHUNKS * K_TOP * C_DIM];

// Branchless insert of v into descending-sorted t[8]. Exact no-op if v <= t[7].
__device__ __forceinline__ void insert8(float (&t)[K_TOP], float v) {
    #pragma unroll
    for (int i = 0; i < K_TOP; ++i) {
        float hi = fmaxf(t[i], v);
        v = fminf(t[i], v);
        t[i] = hi;
    }
}

// Process one channel's group of 8 values.
__device__ __forceinline__ void proc_channel(float (&t)[K_TOP], const float (&f)[8]) {
    // m1 = max, m2 = 2nd max of the group (branchless, 3 ops/elem).
    float m1 = -CUDART_INF_F, m2 = -CUDART_INF_F;
    #pragma unroll
    for (int u = 0; u < 8; ++u) {
        float hi = fmaxf(m1, f[u]);
        m2 = fmaxf(m2, fminf(m1, f[u]));
        m1 = hi;
    }
    // Common case: at most one new top-8 member per group -> branchless insert.
    insert8(t, m1);
    // Rare: group holds >= 2 top-8 members. Insert the remaining 7 values
    // (skip exactly one instance equal to m1 to avoid duplicating it).
    if (m2 > t[K_TOP - 1]) {
        bool skipped = false;
        #pragma unroll
        for (int u = 0; u < 8; ++u) {
            bool sk = (!skipped) && (f[u] == m1);
            skipped = skipped || sk;
            if (!sk) insert8(t, f[u]);
        }
    }
}

__device__ __forceinline__ void proc_group(
    const float4 (&v)[8],
    float (&t0)[K_TOP], float (&t1)[K_TOP], float (&t2)[K_TOP], float (&t3)[K_TOP])
{
    float f[8];
    #pragma unroll
    for (int u = 0; u < 8; ++u) f[u] = v[u].x;
    proc_channel(t0, f);
    #pragma unroll
    for (int u = 0; u < 8; ++u) f[u] = v[u].y;
    proc_channel(t1, f);
    #pragma unroll
    for (int u = 0; u < 8; ++u) f[u] = v[u].z;
    proc_channel(t2, f);
    #pragma unroll
    for (int u = 0; u < 8; ++u) f[u] = v[u].w;
    proc_channel(t3, f);
}

__device__ __forceinline__ void load_group(float4 (&dst)[8], const float4* __restrict__ p, int s) {
    #pragma unroll
    for (int u = 0; u < 8; ++u)
        dst[u] = __ldcs(p + (size_t)(s + u) * LANES);
}

// Pass 1: one block = 4 (batch, chunk) pairs; 64 float4 lanes per pair.
// Warp loads: 32 lanes x 16B = 512B contiguous. Double-buffered groups of 8 s.
__global__ __launch_bounds__(256, 2) void kmax_partial_kernel(
    const float4* __restrict__ x4)
{
    const int sub = threadIdx.x >> 6;          // 0..3
    const int lane = threadIdx.x & 63;         // float4 channel group
    const int pair = blockIdx.x * PAIRS_PER_BLOCK + sub;
    const int batch = pair / CHUNKS;
    const int chunk = pair % CHUNKS;

    const float4* __restrict__ p =
        x4 + ((size_t)batch * S_DIM + (size_t)chunk * CHUNK_S) * LANES + lane;

    float t0[K_TOP], t1[K_TOP], t2[K_TOP], t3[K_TOP];
    #pragma unroll
    for (int i = 0; i < K_TOP; ++i) {
        t0[i] = -CUDART_INF_F; t1[i] = -CUDART_INF_F;
        t2[i] = -CUDART_INF_F; t3[i] = -CUDART_INF_F;
    }

    float4 va[8], vb[8];
    load_group(va, p, 0);
    #pragma unroll 1
    for (int s = 0; s < CHUNK_S; s += 16) {
        load_group(vb, p, s + 8);
        proc_group(va, t0, t1, t2, t3);
        if (s + 16 < CHUNK_S) load_group(va, p, s + 16);
        proc_group(vb, t0, t1, t2, t3);
    }

    // Write partials: [b][chunk][k][c], one STG.128 per k.
    float4* __restrict__ out = (float4*)g_partial
        + ((size_t)pair * K_TOP) * LANES + lane;
    #pragma unroll
    for (int k = 0; k < K_TOP; ++k) {
        float4 o;
        o.x = t0[k]; o.y = t1[k]; o.z = t2[k]; o.w = t3[k];
        out[(size_t)k * LANES] = o;
    }
}

// Pass 2: one thread per (b, c). Merge CHUNKS*K_TOP = 128 L2-resident
// candidates fully branchlessly. Output out[b][k][c].
__global__ __launch_bounds__(128) void kmax_merge_kernel(float* __restrict__ out)
{
    const int tid = blockIdx.x * blockDim.x + threadIdx.x;
    const int b = tid >> 8;
    const int c = tid & (C_DIM - 1);

    float t[K_TOP];
    #pragma unroll
    for (int i = 0; i < K_TOP; ++i) t[i] = -CUDART_INF_F;

    const float* __restrict__ p =
        g_partial + ((size_t)b * CHUNKS * K_TOP) * C_DIM + c;

    #pragma unroll 1
    for (int j = 0; j < CHUNKS * K_TOP; j += 16) {
        float v[16];
        #pragma unroll
        for (int u = 0; u < 16; ++u)
            v[u] = p[(size_t)(j + u) * C_DIM];
        #pragma unroll
        for (int u = 0; u < 16; ++u)
            insert8(t, v[u]);
    }

    float* __restrict__ o = out + (size_t)b * K_TOP * C_DIM + c;
    #pragma unroll
    for (int k = 0; k < K_TOP; ++k)
        o[(size_t)k * C_DIM] = t[k];
}

extern "C" void kernel_launch(void* const* d_in, const int* in_sizes, int n_in,
                              void* d_out, int out_size) {
    const float4* x4 = (const float4*)d_in[0];
    float* out = (float*)d_out;

    kmax_partial_kernel<<<GRID1, 256>>>(x4);
    kmax_merge_kernel<<<(B_DIM * C_DIM) / 128, 128>>>(out);
}

// round 3
// speedup vs baseline: 1.5296x; 1.0061x over previous
#include <cuda_runtime.h>
#include <math_constants.h>

// x: (64, 4096, 256) fp32; top-8 over axis 1 (S), sorted descending -> (64, 8, 256)
#define B_DIM 64
#define S_DIM 4096
#define C_DIM 256
#define K_TOP 8

#define CHUNKS 32
#define CHUNK_S (S_DIM / CHUNKS)        // 128
#define GRID1 (B_DIM * CHUNKS)          // 2048 blocks, 256 threads

// Partial top-8s, transposed layout [b][c][chunk][k]: 16 MiB static scratch.
// For fixed (b,c) the CHUNKS*K_TOP=256 candidates are contiguous (1 KB).
__device__ float g_partial[B_DIM * C_DIM * CHUNKS * K_TOP];

// Branchless insert of v into descending-sorted t[8]. Exact no-op if v <= t[7].
__device__ __forceinline__ void insert8(float (&t)[K_TOP], float v) {
    #pragma unroll
    for (int i = 0; i < K_TOP; ++i) {
        float hi = fmaxf(t[i], v);
        v = fminf(t[i], v);
        t[i] = hi;
    }
}

// Process 8 values: branchless m1/m2 screen + unconditional insert of m1.
// Rare slow path only when the group holds >= 2 top-8 members.
__device__ __forceinline__ void proc8(float (&t)[K_TOP], const float* f) {
    float m1 = -CUDART_INF_F, m2 = -CUDART_INF_F;
    #pragma unroll
    for (int u = 0; u < 8; ++u) {
        float hi = fmaxf(m1, f[u]);
        m2 = fmaxf(m2, fminf(m1, f[u]));
        m1 = hi;
    }
    insert8(t, m1);
    if (m2 > t[K_TOP - 1]) {
        bool skipped = false;
        #pragma unroll
        for (int u = 0; u < 8; ++u) {
            bool sk = (!skipped) && (f[u] == m1);
            skipped = skipped || sk;
            if (!sk) insert8(t, f[u]);
        }
    }
}

// Pass 1: block = (batch, chunk); thread = one channel. Warp loads = 128B lines.
// Low regs (~36) -> 6-7 CTAs/SM -> ~50 warps/SM of TLP to hide DRAM latency.
__global__ __launch_bounds__(256, 6) void kmax_partial_kernel(
    const float* __restrict__ x)
{
    const int batch = blockIdx.x >> 5;         // / CHUNKS
    const int chunk = blockIdx.x & (CHUNKS - 1);
    const int c = threadIdx.x;

    const float* __restrict__ p =
        x + ((size_t)batch * S_DIM + (size_t)chunk * CHUNK_S) * C_DIM + c;

    float t[K_TOP];
    #pragma unroll
    for (int i = 0; i < K_TOP; ++i) t[i] = -CUDART_INF_F;

    #pragma unroll 1
    for (int s = 0; s < CHUNK_S; s += 16) {
        float f[16];
        #pragma unroll
        for (int u = 0; u < 16; ++u)
            f[u] = __ldcs(p + (size_t)(s + u) * C_DIM);
        proc8(t, f);
        proc8(t, f + 8);
    }

    // Write 32B of sorted partials contiguously: [b][c][chunk][k].
    float4* __restrict__ out = (float4*)(g_partial
        + (((size_t)batch * C_DIM + c) * CHUNKS + chunk) * K_TOP);
    out[0] = make_float4(t[0], t[1], t[2], t[3]);
    out[1] = make_float4(t[4], t[5], t[6], t[7]);
}

// Pass 2: one WARP per (b,c). Each lane loads float4 x2 (coalesced 1 KB/warp),
// then 8 rounds of warp-wide extract-max with single-instance removal.
__global__ __launch_bounds__(256) void kmax_merge_kernel(float* __restrict__ out)
{
    const int warp_id = (blockIdx.x * blockDim.x + threadIdx.x) >> 5;
    const int lane = threadIdx.x & 31;
    const int b = warp_id >> 8;                // / C_DIM
    const int c = warp_id & (C_DIM - 1);

    const float4* __restrict__ p4 = (const float4*)(g_partial
        + ((size_t)b * C_DIM + c) * (CHUNKS * K_TOP));

    float v[8];
    {
        float4 a = p4[lane];
        float4 d = p4[lane + 32];
        v[0] = a.x; v[1] = a.y; v[2] = a.z; v[3] = a.w;
        v[4] = d.x; v[5] = d.y; v[6] = d.z; v[7] = d.w;
    }

    float keep = 0.0f;
    #pragma unroll
    for (int k = 0; k < K_TOP; ++k) {
        float m = v[0];
        #pragma unroll
        for (int i = 1; i < 8; ++i) m = fmaxf(m, v[i]);
        float M = m;
        #pragma unroll
        for (int off = 16; off > 0; off >>= 1)
            M = fmaxf(M, __shfl_xor_sync(0xFFFFFFFFu, M, off));
        unsigned ball = __ballot_sync(0xFFFFFFFFu, m == M);
        int leader = __ffs(ball) - 1;
        if (lane == leader) {
            bool done = false;
            #pragma unroll
            for (int i = 0; i < 8; ++i) {
                bool hit = (!done) && (v[i] == M);
                if (hit) v[i] = -CUDART_INF_F;
                done = done || hit;
            }
        }
        if (lane == k) keep = M;
    }

    if (lane < K_TOP)
        out[((size_t)b * K_TOP + lane) * C_DIM + c] = keep;
}

extern "C" void kernel_launch(void* const* d_in, const int* in_sizes, int n_in,
                              void* d_out, int out_size) {
    const float* x = (const float*)d_in[0];
    float* out = (float*)d_out;

    kmax_partial_kernel<<<GRID1, 256>>>(x);
    // 16384 warps = one per (b,c); 2048 blocks x 8 warps.
    kmax_merge_kernel<<<(B_DIM * C_DIM * 32) / 256, 256>>>(out);
}

// round 4
// speedup vs baseline: 2.3441x; 1.5325x over previous
#include <cuda_runtime.h>
#include <math_constants.h>

// x: (64, 4096, 256) fp32; top-8 over axis 1 (S), sorted desc -> (64, 8, 256)
#define B_DIM 64
#define S_DIM 4096
#define C_DIM 256
#define K_TOP 8

#define CHUNKS 32
#define CHUNK_S (S_DIM / CHUNKS)        // 128
#define PAIRS_PER_BLOCK 2               // 256 threads = 2 (b,chunk) pairs x 128 lanes
#define GRID1 (B_DIM * CHUNKS / PAIRS_PER_BLOCK)  // 1024 blocks

// Partials, layout [b][chunk][c][k]: 16 MiB static scratch.
__device__ float g_partial[B_DIM * CHUNKS * C_DIM * K_TOP];

// Compare-exchange keeping max at 'a' (descending order).
__device__ __forceinline__ void ce(float& a, float& b) {
    float hi = fmaxf(a, b);
    float lo = fminf(a, b);
    a = hi; b = lo;
}

// Batcher odd-even mergesort, n=8, 19 CE, descending.
__device__ __forceinline__ void sort8_desc(float (&f)[8]) {
    ce(f[0],f[1]); ce(f[2],f[3]); ce(f[4],f[5]); ce(f[6],f[7]);
    ce(f[0],f[2]); ce(f[1],f[3]); ce(f[4],f[6]); ce(f[5],f[7]);
    ce(f[1],f[2]); ce(f[5],f[6]);
    ce(f[0],f[4]); ce(f[1],f[5]); ce(f[2],f[6]); ce(f[3],f[7]);
    ce(f[2],f[4]); ce(f[3],f[5]);
    ce(f[1],f[2]); ce(f[3],f[4]); ce(f[5],f[6]);
}

// Exact top-8 of union of two descending-sorted 8-lists. t <- result (sorted).
// Step 1: t[i] = max(t[i], g[7-i]) -> bitonic sequence holding the top-8.
// Step 2: 3-stage bitonic merger -> descending.
__device__ __forceinline__ void merge8_desc(float (&t)[8], const float (&g)[8]) {
    #pragma unroll
    for (int i = 0; i < 8; ++i) t[i] = fmaxf(t[i], g[7 - i]);
    ce(t[0],t[4]); ce(t[1],t[5]); ce(t[2],t[6]); ce(t[3],t[7]);
    ce(t[0],t[2]); ce(t[1],t[3]); ce(t[4],t[6]); ce(t[5],t[7]);
    ce(t[0],t[1]); ce(t[2],t[3]); ce(t[4],t[5]); ce(t[6],t[7]);
}

// Pass 1: block = 2 (batch,chunk) pairs; 128 lanes x float2 = 256 channels.
// Fully branchless: per 8 s-values per channel -> sort8 + merge8.
__global__ __launch_bounds__(256, 4) void kmax_partial_kernel(
    const float2* __restrict__ x2)
{
    const int sub  = threadIdx.x >> 7;          // 0..1
    const int lane = threadIdx.x & 127;         // float2 channel group
    const int pair = blockIdx.x * PAIRS_PER_BLOCK + sub;
    const int batch = pair >> 5;                // / CHUNKS
    const int chunk = pair & (CHUNKS - 1);

    const float2* __restrict__ p =
        x2 + ((size_t)batch * S_DIM + (size_t)chunk * CHUNK_S) * (C_DIM / 2) + lane;

    float t0[8], t1[8];
    #pragma unroll
    for (int i = 0; i < 8; ++i) { t0[i] = -CUDART_INF_F; t1[i] = -CUDART_INF_F; }

    #pragma unroll 1
    for (int s = 0; s < CHUNK_S; s += 8) {
        float2 buf[8];
        #pragma unroll
        for (int u = 0; u < 8; ++u)
            buf[u] = __ldcs(p + (size_t)(s + u) * (C_DIM / 2));

        float f[8];
        #pragma unroll
        for (int u = 0; u < 8; ++u) f[u] = buf[u].x;
        sort8_desc(f);
        merge8_desc(t0, f);
        #pragma unroll
        for (int u = 0; u < 8; ++u) f[u] = buf[u].y;
        sort8_desc(f);
        merge8_desc(t1, f);
    }

    // Store 2 channels x 8 sorted floats = 64B contiguous per thread.
    // Layout [b][chunk][c][k]; warp spans 2KB contiguous.
    float4* __restrict__ o = (float4*)(g_partial
        + (((size_t)(batch * CHUNKS + chunk)) * C_DIM + lane * 2) * K_TOP);
    o[0] = make_float4(t0[0], t0[1], t0[2], t0[3]);
    o[1] = make_float4(t0[4], t0[5], t0[6], t0[7]);
    o[2] = make_float4(t1[0], t1[1], t1[2], t1[3]);
    o[3] = make_float4(t1[4], t1[5], t1[6], t1[7]);
}

// Pass 2: one warp per (b,c); lane l holds chunk l's sorted top-8.
// 5 shuffle-exchange levels of the same exact bitonic merge. Branchless.
__global__ __launch_bounds__(256) void kmax_merge_kernel(float* __restrict__ out)
{
    const int warp_id = (blockIdx.x * blockDim.x + threadIdx.x) >> 5;
    const int lane = threadIdx.x & 31;          // == chunk index
    const int b = warp_id >> 8;                 // / C_DIM
    const int c = warp_id & (C_DIM - 1);

    const float4* __restrict__ p4 = (const float4*)g_partial
        + (((size_t)(b * CHUNKS + lane)) * C_DIM + c) * (K_TOP / 4);

    float v[8];
    {
        float4 a = p4[0];
        float4 d = p4[1];
        v[0] = a.x; v[1] = a.y; v[2] = a.z; v[3] = a.w;
        v[4] = d.x; v[5] = d.y; v[6] = d.z; v[7] = d.w;
    }

    #pragma unroll
    for (int d = 16; d >= 1; d >>= 1) {
        float g[8];
        #pragma unroll
        for (int i = 0; i < 8; ++i)
            g[i] = __shfl_xor_sync(0xFFFFFFFFu, v[i], d);
        merge8_desc(v, g);   // both partners end with identical union top-8
    }

    if (lane < K_TOP)
        out[((size_t)b * K_TOP + lane) * C_DIM + c] = v[lane];
}

extern "C" void kernel_launch(void* const* d_in, const int* in_sizes, int n_in,
                              void* d_out, int out_size) {
    const float2* x2 = (const float2*)d_in[0];
    float* out = (float*)d_out;

    kmax_partial_kernel<<<GRID1, 256>>>(x2);
    kmax_merge_kernel<<<(B_DIM * C_DIM * 32) / 256, 256>>>(out);
}

// round 5
// speedup vs baseline: 2.8454x; 1.2139x over previous
#include <cuda_runtime.h>
#include <math_constants.h>

// x: (64, 4096, 256) fp32; top-8 over axis 1 (S), sorted desc -> (64, 8, 256)
#define B_DIM 64
#define S_DIM 4096
#define C_DIM 256
#define K_TOP 8

#define CHUNKS 16
#define CHUNK_S (S_DIM / CHUNKS)        // 256
#define PAIRS_PER_BLOCK 2               // 256 threads = 2 (b,chunk) pairs x 128 lanes
#define GRID1 (B_DIM * CHUNKS / PAIRS_PER_BLOCK)  // 512 blocks

// Partials, layout [b][c][chunk][k]: 8 MiB static scratch.
// For fixed (b,c) the CHUNKS*K_TOP=128 candidates are 512B contiguous.
__device__ float g_partial[B_DIM * C_DIM * CHUNKS * K_TOP];

// Compare-exchange keeping max at 'a' (descending order).
__device__ __forceinline__ void ce(float& a, float& b) {
    float hi = fmaxf(a, b);
    float lo = fminf(a, b);
    a = hi; b = lo;
}

// Batcher odd-even mergesort, n=8, 19 CE, descending.
__device__ __forceinline__ void sort8_desc(float (&f)[8]) {
    ce(f[0],f[1]); ce(f[2],f[3]); ce(f[4],f[5]); ce(f[6],f[7]);
    ce(f[0],f[2]); ce(f[1],f[3]); ce(f[4],f[6]); ce(f[5],f[7]);
    ce(f[1],f[2]); ce(f[5],f[6]);
    ce(f[0],f[4]); ce(f[1],f[5]); ce(f[2],f[6]); ce(f[3],f[7]);
    ce(f[2],f[4]); ce(f[3],f[5]);
    ce(f[1],f[2]); ce(f[3],f[4]); ce(f[5],f[6]);
}

// Exact sorted top-8 of the union of two descending-sorted 8-lists.
__device__ __forceinline__ void merge8_desc(float (&t)[8], const float (&g)[8]) {
    #pragma unroll
    for (int i = 0; i < 8; ++i) t[i] = fmaxf(t[i], g[7 - i]);
    ce(t[0],t[4]); ce(t[1],t[5]); ce(t[2],t[6]); ce(t[3],t[7]);
    ce(t[0],t[2]); ce(t[1],t[3]); ce(t[4],t[6]); ce(t[5],t[7]);
    ce(t[0],t[1]); ce(t[2],t[3]); ce(t[4],t[5]); ce(t[6],t[7]);
}

// Pass 1: block = 2 (batch,chunk) pairs; 128 lanes x float2 = 256 channels.
// 16 s-values per iteration: 16 batched LDG.64 (deep MLP), then branchless
// sort/merge networks per channel.
__global__ __launch_bounds__(256, 3) void kmax_partial_kernel(
    const float2* __restrict__ x2)
{
    const int sub  = threadIdx.x >> 7;          // 0..1
    const int lane = threadIdx.x & 127;         // float2 channel group
    const int pair = blockIdx.x * PAIRS_PER_BLOCK + sub;
    const int batch = pair >> 4;                // / CHUNKS
    const int chunk = pair & (CHUNKS - 1);

    const float2* __restrict__ p =
        x2 + ((size_t)batch * S_DIM + (size_t)chunk * CHUNK_S) * (C_DIM / 2) + lane;

    float t0[8], t1[8];
    #pragma unroll
    for (int i = 0; i < 8; ++i) { t0[i] = -CUDART_INF_F; t1[i] = -CUDART_INF_F; }

    #pragma unroll 1
    for (int s = 0; s < CHUNK_S; s += 16) {
        float2 buf[16];
        #pragma unroll
        for (int u = 0; u < 16; ++u)
            buf[u] = __ldcs(p + (size_t)(s + u) * (C_DIM / 2));

        float f[8], g[8];
        // channel .x
        #pragma unroll
        for (int u = 0; u < 8; ++u) { f[u] = buf[u].x; g[u] = buf[u + 8].x; }
        sort8_desc(f); sort8_desc(g);
        merge8_desc(f, g);      // f = sorted top-8 of the 16
        merge8_desc(t0, f);
        // channel .y
        #pragma unroll
        for (int u = 0; u < 8; ++u) { f[u] = buf[u].y; g[u] = buf[u + 8].y; }
        sort8_desc(f); sort8_desc(g);
        merge8_desc(f, g);
        merge8_desc(t1, f);
    }

    // Store: layout [b][c][chunk][k]; 32B per channel = one full sector.
    const int c0 = lane * 2;
    float4* __restrict__ o0 = (float4*)(g_partial
        + (((size_t)batch * C_DIM + c0) * CHUNKS + chunk) * K_TOP);
    float4* __restrict__ o1 = (float4*)(g_partial
        + (((size_t)batch * C_DIM + c0 + 1) * CHUNKS + chunk) * K_TOP);
    o0[0] = make_float4(t0[0], t0[1], t0[2], t0[3]);
    o0[1] = make_float4(t0[4], t0[5], t0[6], t0[7]);
    o1[0] = make_float4(t1[0], t1[1], t1[2], t1[3]);
    o1[1] = make_float4(t1[4], t1[5], t1[6], t1[7]);
}

// Pass 2: warp = 2 (b,c) pairs. Lane l reads float4s 2l,2l+1 of the warp's
// 2KB contiguous region (fully coalesced, L2-resident). Then 4 shuffle-xor
// bitonic merge levels within each 16-lane half.
__global__ __launch_bounds__(256) void kmax_merge_kernel(float* __restrict__ out)
{
    const int warp_id = (blockIdx.x * blockDim.x + threadIdx.x) >> 5;
    const int lane = threadIdx.x & 31;
    const int sl = lane & 15;                   // chunk index within the pair
    const int gp = warp_id * 2 + (lane >> 4);   // global (b,c) pair
    const int b = gp >> 8;                      // / C_DIM
    const int c = gp & (C_DIM - 1);

    // Warp-contiguous base: pair gp occupies 128 floats = 32 float4s.
    const float4* __restrict__ p4 =
        (const float4*)g_partial + (size_t)warp_id * 64 + lane * 2;

    float v[8];
    {
        float4 a = p4[0];
        float4 d = p4[1];
        v[0] = a.x; v[1] = a.y; v[2] = a.z; v[3] = a.w;
        v[4] = d.x; v[5] = d.y; v[6] = d.z; v[7] = d.w;
    }

    #pragma unroll
    for (int d = 8; d >= 1; d >>= 1) {
        float g[8];
        #pragma unroll
        for (int i = 0; i < 8; ++i)
            g[i] = __shfl_xor_sync(0xFFFFFFFFu, v[i], d);
        merge8_desc(v, g);
    }

    if (sl < K_TOP)
        out[((size_t)b * K_TOP + sl) * C_DIM + c] = v[sl];
}

extern "C" void kernel_launch(void* const* d_in, const int* in_sizes, int n_in,
                              void* d_out, int out_size) {
    const float2* x2 = (const float2*)d_in[0];
    float* out = (float*)d_out;

    kmax_partial_kernel<<<GRID1, 256>>>(x2);
    // 16384 (b,c) pairs / 2 per warp = 8192 warps = 1024 blocks x 8 warps.
    kmax_merge_kernel<<<1024, 256>>>(out);
}